// round 9
// baseline (speedup 1.0000x reference)
#include <cuda_runtime.h>
#include <math.h>
#include <stdint.h>

#define NBLK 3
#define BD 8
#define HWQ 4096   // 64*64
#define NCH 64     // NC (channels per DAT block)
#define NS  256    // Hk*Wk = 16*16
#define HCD 16     // head channels
#define TABN 16129 // 127*127
#define TABP 16384 // padded dual-table stride
#define LOG2E 1.4426950408889634f

// ---- static device scratch (no runtime allocation allowed) ----
__device__ float  g_Q[NBLK*BD*NCH*HWQ];   // q projections      [blk][b][c][hw]
__device__ float  g_O[NBLK*BD*NCH*HWQ];   // attention outputs  [blk][b][c][hw]
__device__ float  g_K[NBLK*BD*NCH*NS];    // keys   [blk][b][c][n]
__device__ float  g_V[NBLK*BD*NCH*NS];    // values [blk][b][c][n]
__device__ float4 g_BP[NBLK*BD*NS];       // bias params per n: (y0*127+x0, wy, wx, 0)
__device__ float2 g_POS[NBLK*BD*NS];      // normalized sample pos (py,px)
__device__ float2 g_TAB2[NBLK*4*TABP];    // dual RPE tables: (t[i], t[i+1]), zero-padded

// ---- packed f32x2 helpers (Blackwell sm_103a) ----
typedef unsigned long long u64t;
__device__ __forceinline__ u64t pk2(float a, float b) {
    u64t r; asm("mov.b64 %0, {%1, %2};" : "=l"(r) : "f"(a), "f"(b)); return r;
}
__device__ __forceinline__ float2 upk2(u64t v) {
    float x, y; asm("mov.b64 {%0, %1}, %2;" : "=f"(x), "=f"(y) : "l"(v));
    return make_float2(x, y);
}
__device__ __forceinline__ u64t fma2(u64t a, u64t b, u64t c) {
    u64t r; asm("fma.rn.f32x2 %0, %1, %2, %3;" : "=l"(r) : "l"(a), "l"(b), "l"(c));
    return r;
}
__device__ __forceinline__ u64t mul2(u64t a, u64t b) {
    u64t r; asm("mul.rn.f32x2 %0, %1, %2;" : "=l"(r) : "l"(a), "l"(b));
    return r;
}
__device__ __forceinline__ u64t add2(u64t a, u64t b) {
    u64t r; asm("add.rn.f32x2 %0, %1, %2;" : "=l"(r) : "l"(a), "l"(b));
    return r;
}
__device__ __forceinline__ float ex2f(float x) {
    float r; asm("ex2.approx.ftz.f32 %0, %1;" : "=f"(r) : "f"(x)); return r;
}

// ============================================================================
// Kernel T: build dual tables. grid = 12 tables * 8 chunks = 96
// ============================================================================
__global__ __launch_bounds__(256) void k_tab2(const float* __restrict__ rpe)
{
    int t = blockIdx.x >> 3, q = blockIdx.x & 7;
    const float* src = rpe + (size_t)t * TABN;
    float2* dst = g_TAB2 + (size_t)t * TABP;
    #pragma unroll
    for (int k = 0; k < 8; ++k) {
        int i = q*2048 + k*256 + threadIdx.x;
        float a = (i < TABN)     ? src[i]   : 0.f;
        float b = (i+1 < TABN)   ? src[i+1] : 0.f;
        dst[i] = make_float2(a, b);
    }
}

// ============================================================================
// Kernel A: q-projection + depthwise conv 4x4 s4 + LN/GELU/offset head fused.
// grid = 384 (3 blk * 8 b * 16 tiles of 4 image rows), 256 threads.
// ============================================================================
__global__ __launch_bounds__(256) void k_qproj_dw(
    const float* __restrict__ x1, const float* __restrict__ x2,
    const float* __restrict__ pqw, const float* __restrict__ pqb,
    const float* __restrict__ dww, const float* __restrict__ dwb,
    const float* __restrict__ lng, const float* __restrict__ lnb,
    const float* __restrict__ pww)
{
    __shared__ float wsT[64*64];
    __shared__ float bs[64];
    __shared__ float sq[16*256];
    __shared__ float swdw[64*16];
    __shared__ float sdwb[64];
    __shared__ float sdw[16*69];

    int bx = blockIdx.x;
    int tile = bx & 15, b = (bx >> 4) & 7, blk = bx >> 7;
    int bb = blk*BD + b;
    const float* xin = (blk == 0 ? x1 : x2) + (size_t)b * 128 * HWQ;
    int tid = threadIdx.x;

    for (int i = tid; i < 4096; i += 256) {
        int c = i >> 6, o = i & 63;
        wsT[c*64 + o] = pqw[blk*4096 + o*64 + c];
    }
    for (int i = tid; i < 1024; i += 256)
        swdw[i] = dww[blk*NCH*16 + i];
    if (tid < 64) {
        bs[tid]   = pqb[blk*64 + tid];
        sdwb[tid] = dwb[blk*64 + tid];
    }
    __syncthreads();

    int hw = tile*256 + tid;
    float* qout = g_Q + (size_t)bb * NCH * HWQ;

    float acc[64];
    #pragma unroll
    for (int o = 0; o < 64; ++o) acc[o] = bs[o];
    #pragma unroll 2
    for (int c = 0; c < 64; ++c) {
        float xv = __ldg(&xin[c*HWQ + hw]);
        const float4* wr = reinterpret_cast<const float4*>(&wsT[c*64]);
        #pragma unroll
        for (int o4 = 0; o4 < 16; ++o4) {
            float4 w = wr[o4];
            acc[o4*4+0] = fmaf(w.x, xv, acc[o4*4+0]);
            acc[o4*4+1] = fmaf(w.y, xv, acc[o4*4+1]);
            acc[o4*4+2] = fmaf(w.z, xv, acc[o4*4+2]);
            acc[o4*4+3] = fmaf(w.w, xv, acc[o4*4+3]);
        }
    }
    #pragma unroll
    for (int o = 0; o < 64; ++o) qout[o*HWQ + hw] = acc[o];

    // ---- fused depthwise conv ----
    int cl = tid >> 4, ox = tid & 15;
    #pragma unroll
    for (int q4 = 0; q4 < 4; ++q4) {
        __syncthreads();
        #pragma unroll
        for (int cc = 0; cc < 16; ++cc)
            sq[cc*256 + tid] = acc[q4*16 + cc];
        __syncthreads();
        int c = q4*16 + cl;
        float a = sdwb[c];
        const float* w = &swdw[c*16];
        const float* sp = sq + cl*256 + ox*4;
        #pragma unroll
        for (int ky = 0; ky < 4; ++ky)
            #pragma unroll
            for (int kx = 0; kx < 4; ++kx)
                a = fmaf(sp[ky*64 + kx], w[ky*4 + kx], a);
        sdw[ox*69 + c] = a;
    }
    __syncthreads();

    // ---- fused offset head ----
    {
        int warp = tid >> 5, lane = tid & 31;
        int half = lane >> 4, hl = lane & 15;
        int ln = warp*2 + half;
        float vv[4];
        float s1 = 0.f, s2 = 0.f;
        #pragma unroll
        for (int k = 0; k < 4; ++k) {
            vv[k] = sdw[ln*69 + hl*4 + k];
            s1 += vv[k]; s2 += vv[k]*vv[k];
        }
        #pragma unroll
        for (int off = 8; off; off >>= 1) {
            s1 += __shfl_xor_sync(0xffffffffu, s1, off);
            s2 += __shfl_xor_sync(0xffffffffu, s2, off);
        }
        float mu  = s1 * (1.f/64.f);
        float var = s2 * (1.f/64.f) - mu*mu;
        float rs  = rsqrtf(var + 1e-5f);
        float offy = 0.f, offx = 0.f;
        #pragma unroll
        for (int k = 0; k < 4; ++k) {
            int c = hl*4 + k;
            float t = (vv[k] - mu) * rs * __ldg(&lng[blk*64 + c]) + __ldg(&lnb[blk*64 + c]);
            float gl = 0.5f * t * (1.f + erff(t * 0.70710678118654752f));
            offy = fmaf(__ldg(&pww[blk*128 + c]),      gl, offy);
            offx = fmaf(__ldg(&pww[blk*128 + 64 + c]), gl, offx);
        }
        #pragma unroll
        for (int off = 8; off; off >>= 1) {
            offy += __shfl_xor_sync(0xffffffffu, offy, off);
            offx += __shfl_xor_sync(0xffffffffu, offx, off);
        }
        if (hl == 0) {
            int oy = tile;
            float refy = (2.f*((float)oy + 0.5f)) * (1.f/15.f) - 1.f;
            float refx = (2.f*((float)ln + 0.5f)) * (1.f/15.f) - 1.f;
            float py = fminf(fmaxf(offy + refy, -1.f), 1.f);
            float px = fminf(fmaxf(offx + refx, -1.f), 1.f);
            float ay = 31.5f*(1.f - py), ax = 31.5f*(1.f - px);
            float by0 = floorf(ay), bx0 = floorf(ax);
            int n = tile*16 + ln;
            g_BP[bb*NS + n]  = make_float4(by0*127.f + bx0, ay - by0, ax - bx0, 0.f);
            g_POS[bb*NS + n] = make_float2(py, px);
        }
    }
}

// ============================================================================
// Kernel B3: deformable gather + k/v projections.
// grid = 384 (3 blk * 8 b * 16 n-chunks of 16), 256 threads = (nl 16, cg 16).
// ============================================================================
__global__ __launch_bounds__(256) void k_gkv(
    const float* __restrict__ x0, const float* __restrict__ x1,
    const float* __restrict__ pkw, const float* __restrict__ pkb,
    const float* __restrict__ pvw, const float* __restrict__ pvb)
{
    extern __shared__ float sm[];
    float* buf  = sm;               // [16][65]
    float* skwT = sm + 16*65;       // [c][o] 4096
    float* svwT = skwT + 4096;      // 4096

    int bx = blockIdx.x;
    int chunk = bx & 15, b = (bx >> 4) & 7, blk = bx >> 7;
    const float* kvsrc = (blk == 2 ? x1 : x0) + (size_t)b * 128 * HWQ;
    int tid = threadIdx.x;
    int nl = tid & 15, cg = tid >> 4;
    int n = chunk*16 + nl;

    for (int i = tid; i < 4096; i += 256) {
        int o = i >> 6, c = i & 63;
        skwT[c*64 + o] = pkw[blk*4096 + i];
        svwT[c*64 + o] = pvw[blk*4096 + i];
    }

    float2 pos = g_POS[(blk*BD + b)*NS + n];
    float sy = (pos.x + 1.f)*31.5f, sx = (pos.y + 1.f)*31.5f;
    float fy = floorf(sy), fx = floorf(sx);
    int iy0 = (int)fy, ix0 = (int)fx;
    float wby = sy - fy, wbx = sx - fx;
    int iy1 = min(iy0 + 1, 63), ix1 = min(ix0 + 1, 63);
    float w00 = (1.f-wby)*(1.f-wbx), w01 = (1.f-wby)*wbx;
    float w10 = wby*(1.f-wbx),       w11 = wby*wbx;

    float tap[16];
    #pragma unroll
    for (int cc = 0; cc < 4; ++cc) {
        const float* ip = kvsrc + (size_t)(cg*4 + cc)*HWQ;
        tap[cc*4+0] = __ldg(&ip[iy0*64 + ix0]);
        tap[cc*4+1] = __ldg(&ip[iy0*64 + ix1]);
        tap[cc*4+2] = __ldg(&ip[iy1*64 + ix0]);
        tap[cc*4+3] = __ldg(&ip[iy1*64 + ix1]);
    }
    #pragma unroll
    for (int cc = 0; cc < 4; ++cc)
        buf[nl*65 + cg*4 + cc] = w00*tap[cc*4+0] + w01*tap[cc*4+1]
                               + w10*tap[cc*4+2] + w11*tap[cc*4+3];
    __syncthreads();

    float ak[4], av[4];
    #pragma unroll
    for (int oo = 0; oo < 4; ++oo) {
        ak[oo] = __ldg(&pkb[blk*64 + cg*4 + oo]);
        av[oo] = __ldg(&pvb[blk*64 + cg*4 + oo]);
    }
    #pragma unroll 8
    for (int c = 0; c < 64; ++c) {
        float xv = buf[nl*65 + c];
        float4 kw = *reinterpret_cast<const float4*>(&skwT[c*64 + cg*4]);
        float4 vw = *reinterpret_cast<const float4*>(&svwT[c*64 + cg*4]);
        ak[0] = fmaf(kw.x, xv, ak[0]); ak[1] = fmaf(kw.y, xv, ak[1]);
        ak[2] = fmaf(kw.z, xv, ak[2]); ak[3] = fmaf(kw.w, xv, ak[3]);
        av[0] = fmaf(vw.x, xv, av[0]); av[1] = fmaf(vw.y, xv, av[1]);
        av[2] = fmaf(vw.z, xv, av[2]); av[3] = fmaf(vw.w, xv, av[3]);
    }

    float* kout = g_K + (size_t)(blk*BD + b)*NCH*NS;
    float* vout = g_V + (size_t)(blk*BD + b)*NCH*NS;
    #pragma unroll
    for (int oo = 0; oo < 4; ++oo) {
        int o = cg*4 + oo;
        kout[o*NS + n] = ak[oo];
        vout[o*NS + n] = av[oo];
    }
}

// ============================================================================
// Kernel D: attention. Packed f32x2, depth-2 pipeline on bias-table chain,
// tree-split QK chains, exp via bare ex2 (log2e folded into q and bias wts).
// ============================================================================
__global__ __launch_bounds__(256, 2) void k_attn()
{
    extern __shared__ float sm[];
    float*      Ks    = sm;                            // 4096 floats
    float*      Vs    = sm + 4096;                     // 4096 floats
    ulonglong2* ppw   = (ulonglong2*)(sm + 8192);      // 256 * 16B
    int*        pbase = (int*)(sm + 8192 + 1024);      // 256

    int bx = blockIdx.x;
    int tile = bx & 7, head = (bx >> 3) & 3, bb = bx >> 5;
    int tid = threadIdx.x;

    const u64t* tab = (const u64t*)(g_TAB2 + (size_t)((bb >> 3)*4 + head) * TABP);

    const float* kg = g_K + (size_t)(bb*NCH + head*HCD) * NS;
    const float* vg = g_V + (size_t)(bb*NCH + head*HCD) * NS;
    #pragma unroll
    for (int c4 = 0; c4 < 4; ++c4) {
        float a0 = kg[(c4*4+0)*NS + tid], a1 = kg[(c4*4+1)*NS + tid];
        float a2 = kg[(c4*4+2)*NS + tid], a3 = kg[(c4*4+3)*NS + tid];
        reinterpret_cast<float4*>(Ks)[tid*4 + c4] = make_float4(a0,a1,a2,a3);
        a0 = vg[(c4*4+0)*NS + tid]; a1 = vg[(c4*4+1)*NS + tid];
        a2 = vg[(c4*4+2)*NS + tid]; a3 = vg[(c4*4+3)*NS + tid];
        reinterpret_cast<float4*>(Vs)[tid*4 + c4] = make_float4(a0,a1,a2,a3);
    }
    {
        float4 bp = g_BP[bb*NS + tid];
        float wy = bp.y, wx = bp.z;
        ulonglong2 w;
        // log2e folded into bias weights
        w.x = pk2(LOG2E*(1.f-wy)*(1.f-wx), LOG2E*(1.f-wy)*wx);
        w.y = pk2(LOG2E*wy*(1.f-wx),       LOG2E*wy*wx);
        ppw[tid] = w;
        pbase[tid] = (int)bp.x;
    }
    __syncthreads();

    int x = tid & 63, yp = tid >> 6;
    int y = tile*8 + yp*2;
    int m1 = y*64 + x;
    int rbase = y*127 + x;
    const float* qg = g_Q + (size_t)(bb*NCH + head*HCD) * HWQ;
    const float QS = 0.25f * LOG2E;           // scale + log2e folded into q
    u64t q1p[8], q2p[8];
    #pragma unroll
    for (int j = 0; j < 8; ++j) {
        q1p[j] = pk2(QS*qg[(2*j)*HWQ + m1],      QS*qg[(2*j+1)*HWQ + m1]);
        q2p[j] = pk2(QS*qg[(2*j)*HWQ + m1 + 64], QS*qg[(2*j+1)*HWQ + m1 + 64]);
    }

    u64t acc1p[8], acc2p[8];
    u64t zero = pk2(0.f, 0.f);
    #pragma unroll
    for (int j = 0; j < 8; ++j) { acc1p[j] = zero; acc2p[j] = zero; }
    float ss1 = 0.f, ss2 = 0.f;

    const ulonglong2* Ksu = (const ulonglong2*)Ks;
    const ulonglong2* Vsu = (const ulonglong2*)Vs;

    ulonglong2 wpp[2];
    u64t tt0[2], tt1[2], tt2[2];
    {
        int a0 = pbase[0] + rbase, a1 = pbase[1] + rbase;
        wpp[0] = ppw[0]; wpp[1] = ppw[1];
        tt0[0] = __ldg(&tab[a0]); tt1[0] = __ldg(&tab[a0+127]); tt2[0] = __ldg(&tab[a0+254]);
        tt0[1] = __ldg(&tab[a1]); tt1[1] = __ldg(&tab[a1+127]); tt2[1] = __ldg(&tab[a1+254]);
    }

    #pragma unroll 4
    for (int n = 0; n < 256; ++n) {
        int cur = n & 1;
        ulonglong2 wp = wpp[cur];
        u64t t0 = tt0[cur], t1 = tt1[cur], t2 = tt2[cur];
        int np = n + 2;
        if (np < 256) {
            int a = pbase[np] + rbase;
            wpp[cur] = ppw[np];
            tt0[cur] = __ldg(&tab[a]);
            tt1[cur] = __ldg(&tab[a + 127]);
            tt2[cur] = __ldg(&tab[a + 254]);
        }

        u64t b1p = fma2(wp.y, t1, mul2(wp.x, t0));
        u64t b2p = fma2(wp.y, t2, mul2(wp.x, t1));

        ulonglong2 kA = Ksu[n*4+0], kB = Ksu[n*4+1], kC = Ksu[n*4+2], kD = Ksu[n*4+3];
        // tree-split dot products (two 4-deep chains each)
        u64t d1a = mul2(q1p[0], kA.x);
        d1a = fma2(q1p[1], kA.y, d1a); d1a = fma2(q1p[2], kB.x, d1a);
        d1a = fma2(q1p[3], kB.y, d1a);
        u64t d1b = mul2(q1p[4], kC.x);
        d1b = fma2(q1p[5], kC.y, d1b); d1b = fma2(q1p[6], kD.x, d1b);
        d1b = fma2(q1p[7], kD.y, d1b);
        u64t d2a = mul2(q2p[0], kA.x);
        d2a = fma2(q2p[1], kA.y, d2a); d2a = fma2(q2p[2], kB.x, d2a);
        d2a = fma2(q2p[3], kB.y, d2a);
        u64t d2b = mul2(q2p[4], kC.x);
        d2b = fma2(q2p[5], kC.y, d2b); d2b = fma2(q2p[6], kD.x, d2b);
        d2b = fma2(q2p[7], kD.y, d2b);

        float2 l1 = upk2(add2(add2(d1a, d1b), b1p));
        float2 l2 = upk2(add2(add2(d2a, d2b), b2p));
        float p1 = ex2f(l1.x + l1.y); ss1 += p1;
        float p2 = ex2f(l2.x + l2.y); ss2 += p2;
        u64t p1p = pk2(p1, p1), p2p = pk2(p2, p2);

        ulonglong2 vA = Vsu[n*4+0], vB = Vsu[n*4+1], vC = Vsu[n*4+2], vD = Vsu[n*4+3];
        acc1p[0] = fma2(p1p, vA.x, acc1p[0]); acc2p[0] = fma2(p2p, vA.x, acc2p[0]);
        acc1p[1] = fma2(p1p, vA.y, acc1p[1]); acc2p[1] = fma2(p2p, vA.y, acc2p[1]);
        acc1p[2] = fma2(p1p, vB.x, acc1p[2]); acc2p[2] = fma2(p2p, vB.x, acc2p[2]);
        acc1p[3] = fma2(p1p, vB.y, acc1p[3]); acc2p[3] = fma2(p2p, vB.y, acc2p[3]);
        acc1p[4] = fma2(p1p, vC.x, acc1p[4]); acc2p[4] = fma2(p2p, vC.x, acc2p[4]);
        acc1p[5] = fma2(p1p, vC.y, acc1p[5]); acc2p[5] = fma2(p2p, vC.y, acc2p[5]);
        acc1p[6] = fma2(p1p, vD.x, acc1p[6]); acc2p[6] = fma2(p2p, vD.x, acc2p[6]);
        acc1p[7] = fma2(p1p, vD.y, acc1p[7]); acc2p[7] = fma2(p2p, vD.y, acc2p[7]);
    }

    float i1 = 1.f / ss1, i2 = 1.f / ss2;
    float* og = g_O + (size_t)(bb*NCH + head*HCD) * HWQ;
    #pragma unroll
    for (int j = 0; j < 8; ++j) {
        float2 a1 = upk2(acc1p[j]), a2 = upk2(acc2p[j]);
        og[(2*j  )*HWQ + m1]      = a1.x * i1;
        og[(2*j+1)*HWQ + m1]      = a1.y * i1;
        og[(2*j  )*HWQ + m1 + 64] = a2.x * i2;
        og[(2*j+1)*HWQ + m1 + 64] = a2.y * i2;
    }
}

// ============================================================================
// Kernel E: output projection + residual, packed f32x2 with splatted weights.
// grid = 512 (lvl in {1,2} * 8 b * 32 tiles of 128 hw), 256 threads =
// 64 hw-pairs x 4 o-quarters. smem: packed (w,w) per block (32KB each).
// ============================================================================
__global__ __launch_bounds__(256) void k_out(
    const float* __restrict__ x1, const float* __restrict__ x2,
    const float* __restrict__ poww, const float* __restrict__ pob,
    float* __restrict__ out)
{
    extern __shared__ u64t smw[];
    u64t* wp0 = smw;            // [c][o] packed, 4096
    u64t* wp1 = smw + 4096;     // 4096 (lvl2 only)
    u64t* bsp = smw + 8192;     // 64 packed biases

    int bx = blockIdx.x;
    int tile = bx & 31, b = (bx >> 5) & 7, lvl = 1 + (bx >> 8);
    const float* xl = (lvl == 1 ? x1 : x2) + (size_t)b * 128 * HWQ;
    float* outp = out + (size_t)(lvl*BD + b) * 128 * HWQ;
    int tid = threadIdx.x;
    int hp = tid & 63, oq = tid >> 6;
    int hw2 = tile*128 + hp*2;

    int blk0 = (lvl == 1) ? 0 : 1;
    int nb   = (lvl == 1) ? 1 : 2;

    for (int i = tid; i < 4096; i += 256) {
        int c = i >> 6, o = i & 63;
        float v0 = poww[blk0*4096 + o*64 + c];
        wp0[c*64 + o] = pk2(v0, v0);
        if (nb == 2) {
            float v1 = poww[(blk0+1)*4096 + o*64 + c];
            wp1[c*64 + o] = pk2(v1, v1);
        }
    }
    if (tid < 64) {
        float s = pob[blk0*64 + tid];
        if (nb == 2) s += pob[(blk0+1)*64 + tid];
        bsp[tid] = pk2(s, s);
    }
    __syncthreads();

    const float* o0 = g_O + (size_t)(blk0*BD + b) * NCH * HWQ;
    const float* o1 = g_O + (size_t)((blk0+1)*BD + b) * NCH * HWQ;

    u64t acc[16];
    #pragma unroll
    for (int j = 0; j < 16; ++j) {
        int o = oq*16 + j;
        u64t xlp = *reinterpret_cast<const u64t*>(xl + (size_t)(64 + o)*HWQ + hw2);
        acc[j] = add2(xlp, bsp[o]);
    }

    #pragma unroll 4
    for (int c = 0; c < 64; ++c) {
        u64t a0 = *reinterpret_cast<const u64t*>(o0 + (size_t)c*HWQ + hw2);
        const ulonglong2* wr = reinterpret_cast<const ulonglong2*>(&wp0[c*64 + oq*16]);
        #pragma unroll
        for (int j2 = 0; j2 < 8; ++j2) {
            ulonglong2 w = wr[j2];
            acc[j2*2+0] = fma2(w.x, a0, acc[j2*2+0]);
            acc[j2*2+1] = fma2(w.y, a0, acc[j2*2+1]);
        }
    }
    if (nb == 2) {
        #pragma unroll 4
        for (int c = 0; c < 64; ++c) {
            u64t a1 = *reinterpret_cast<const u64t*>(o1 + (size_t)c*HWQ + hw2);
            const ulonglong2* wr = reinterpret_cast<const ulonglong2*>(&wp1[c*64 + oq*16]);
            #pragma unroll
            for (int j2 = 0; j2 < 8; ++j2) {
                ulonglong2 w = wr[j2];
                acc[j2*2+0] = fma2(w.x, a1, acc[j2*2+0]);
                acc[j2*2+1] = fma2(w.y, a1, acc[j2*2+1]);
            }
        }
    }
    #pragma unroll
    for (int j = 0; j < 16; ++j) {
        int o = oq*16 + j;
        *reinterpret_cast<u64t*>(outp + (size_t)(64 + o)*HWQ + hw2) = acc[j];
    }
}

// ============================================================================
extern "C" void kernel_launch(void* const* d_in, const int* in_sizes, int n_in,
                              void* d_out, int out_size)
{
    const float* x0  = (const float*)d_in[0];
    const float* x1  = (const float*)d_in[1];
    const float* x2  = (const float*)d_in[2];
    const float* pqw = (const float*)d_in[3];
    const float* pqb = (const float*)d_in[4];
    const float* dww = (const float*)d_in[5];
    const float* dwb = (const float*)d_in[6];
    const float* lng = (const float*)d_in[7];
    const float* lnb = (const float*)d_in[8];
    const float* pww = (const float*)d_in[9];
    const float* pkw = (const float*)d_in[10];
    const float* pkb = (const float*)d_in[11];
    const float* pvw = (const float*)d_in[12];
    const float* pvb = (const float*)d_in[13];
    const float* pow_ = (const float*)d_in[14];
    const float* pob = (const float*)d_in[15];
    const float* rpe = (const float*)d_in[16];
    float* out = (float*)d_out;

    const int gkv_smem = (16*65 + 4096 + 4096) * 4;            // 36928 B
    const int d_smem   = 8192*4 + 256*16 + 256*4;              // 37888 B
    const int out_smem = (8192 + 64) * 8;                      // 66048 B
    cudaFuncSetAttribute(k_gkv,  cudaFuncAttributeMaxDynamicSharedMemorySize, gkv_smem);
    cudaFuncSetAttribute(k_attn, cudaFuncAttributeMaxDynamicSharedMemorySize, d_smem);
    cudaFuncSetAttribute(k_out,  cudaFuncAttributeMaxDynamicSharedMemorySize, out_smem);

    const size_t LVL = (size_t)BD * 128 * HWQ;
    const size_t BAT = (size_t)128 * HWQ;

    cudaMemcpyAsync(out, x0, LVL * 4, cudaMemcpyDeviceToDevice);
    for (int b = 0; b < BD; ++b)
        cudaMemcpyAsync(out + LVL + b*BAT, x1 + b*BAT, (BAT/2) * 4,
                        cudaMemcpyDeviceToDevice);
    for (int b = 0; b < BD; ++b)
        cudaMemcpyAsync(out + 2*LVL + b*BAT, x2 + b*BAT, (BAT/2) * 4,
                        cudaMemcpyDeviceToDevice);

    k_tab2<<<96, 256>>>(rpe);
    k_qproj_dw<<<384, 256>>>(x1, x2, pqw, pqb, dww, dwb, lng, lnb, pww);
    k_gkv<<<384, 256, gkv_smem>>>(x0, x1, pkw, pkb, pvw, pvb);
    k_attn<<<768, 256, d_smem>>>();
    k_out<<<512, 256, out_smem>>>(x1, x2, pow_, pob, out);
}

// round 10
// speedup vs baseline: 1.0297x; 1.0297x over previous
#include <cuda_runtime.h>
#include <cuda_fp16.h>
#include <math.h>
#include <stdint.h>

#define NBLK 3
#define BD 8
#define HWQ 4096   // 64*64
#define NCH 64     // NC (channels per DAT block)
#define NS  256    // Hk*Wk = 16*16
#define HCD 16     // head channels
#define TABN 16129 // 127*127
#define TABP 16384 // padded dual-table stride
#define LOG2E 1.4426950408889634f

// ---- static device scratch (no runtime allocation allowed) ----
__device__ float   g_Q[NBLK*BD*NCH*HWQ];   // q projections      [blk][b][c][hw]
__device__ float   g_O[NBLK*BD*NCH*HWQ];   // attention outputs  [blk][b][c][hw]
__device__ float   g_K[NBLK*BD*NCH*NS];    // keys   [blk][b][c][n]
__device__ float   g_V[NBLK*BD*NCH*NS];    // values [blk][b][c][n]
__device__ float4  g_BP[NBLK*BD*NS];       // bias params per n: (y0*127+x0, wy, wx, 0)
__device__ float2  g_POS[NBLK*BD*NS];      // normalized sample pos (py,px)
__device__ __half2 g_TABH[NBLK*4*TABP];    // dual RPE tables in fp16: (t[i], t[i+1])

// ---- packed f32x2 helpers (Blackwell sm_103a) ----
typedef unsigned long long u64t;
__device__ __forceinline__ u64t pk2(float a, float b) {
    u64t r; asm("mov.b64 %0, {%1, %2};" : "=l"(r) : "f"(a), "f"(b)); return r;
}
__device__ __forceinline__ float2 upk2(u64t v) {
    float x, y; asm("mov.b64 {%0, %1}, %2;" : "=f"(x), "=f"(y) : "l"(v));
    return make_float2(x, y);
}
__device__ __forceinline__ u64t fma2(u64t a, u64t b, u64t c) {
    u64t r; asm("fma.rn.f32x2 %0, %1, %2, %3;" : "=l"(r) : "l"(a), "l"(b), "l"(c));
    return r;
}
__device__ __forceinline__ u64t mul2(u64t a, u64t b) {
    u64t r; asm("mul.rn.f32x2 %0, %1, %2;" : "=l"(r) : "l"(a), "l"(b));
    return r;
}
__device__ __forceinline__ u64t add2(u64t a, u64t b) {
    u64t r; asm("add.rn.f32x2 %0, %1, %2;" : "=l"(r) : "l"(a), "l"(b));
    return r;
}
__device__ __forceinline__ float ex2f(float x) {
    float r; asm("ex2.approx.ftz.f32 %0, %1;" : "=f"(r) : "f"(x)); return r;
}
// half2 (as u32) -> packed f32x2 u64
__device__ __forceinline__ u64t h2u64(uint32_t h) {
    float2 f = __half22float2(*reinterpret_cast<__half2*>(&h));
    return pk2(f.x, f.y);
}

// ============================================================================
// Kernel T: build fp16 dual tables. grid = 12 tables * 8 chunks = 96
// ============================================================================
__global__ __launch_bounds__(256) void k_tab2(const float* __restrict__ rpe)
{
    int t = blockIdx.x >> 3, q = blockIdx.x & 7;
    const float* src = rpe + (size_t)t * TABN;
    __half2* dst = g_TABH + (size_t)t * TABP;
    #pragma unroll
    for (int k = 0; k < 8; ++k) {
        int i = q*2048 + k*256 + threadIdx.x;
        float a = (i < TABN)     ? src[i]   : 0.f;
        float b = (i+1 < TABN)   ? src[i+1] : 0.f;
        dst[i] = __floats2half2_rn(a, b);
    }
}

// ============================================================================
// Kernel A: q-projection + depthwise conv 4x4 s4 + LN/GELU/offset head fused.
// grid = 384 (3 blk * 8 b * 16 tiles of 4 image rows), 256 threads.
// ============================================================================
__global__ __launch_bounds__(256) void k_qproj_dw(
    const float* __restrict__ x1, const float* __restrict__ x2,
    const float* __restrict__ pqw, const float* __restrict__ pqb,
    const float* __restrict__ dww, const float* __restrict__ dwb,
    const float* __restrict__ lng, const float* __restrict__ lnb,
    const float* __restrict__ pww)
{
    __shared__ float wsT[64*64];
    __shared__ float bs[64];
    __shared__ float sq[16*256];
    __shared__ float swdw[64*16];
    __shared__ float sdwb[64];
    __shared__ float sdw[16*69];

    int bx = blockIdx.x;
    int tile = bx & 15, b = (bx >> 4) & 7, blk = bx >> 7;
    int bb = blk*BD + b;
    const float* xin = (blk == 0 ? x1 : x2) + (size_t)b * 128 * HWQ;
    int tid = threadIdx.x;

    for (int i = tid; i < 4096; i += 256) {
        int c = i >> 6, o = i & 63;
        wsT[c*64 + o] = pqw[blk*4096 + o*64 + c];
    }
    for (int i = tid; i < 1024; i += 256)
        swdw[i] = dww[blk*NCH*16 + i];
    if (tid < 64) {
        bs[tid]   = pqb[blk*64 + tid];
        sdwb[tid] = dwb[blk*64 + tid];
    }
    __syncthreads();

    int hw = tile*256 + tid;
    float* qout = g_Q + (size_t)bb * NCH * HWQ;

    float acc[64];
    #pragma unroll
    for (int o = 0; o < 64; ++o) acc[o] = bs[o];
    #pragma unroll 2
    for (int c = 0; c < 64; ++c) {
        float xv = __ldg(&xin[c*HWQ + hw]);
        const float4* wr = reinterpret_cast<const float4*>(&wsT[c*64]);
        #pragma unroll
        for (int o4 = 0; o4 < 16; ++o4) {
            float4 w = wr[o4];
            acc[o4*4+0] = fmaf(w.x, xv, acc[o4*4+0]);
            acc[o4*4+1] = fmaf(w.y, xv, acc[o4*4+1]);
            acc[o4*4+2] = fmaf(w.z, xv, acc[o4*4+2]);
            acc[o4*4+3] = fmaf(w.w, xv, acc[o4*4+3]);
        }
    }
    #pragma unroll
    for (int o = 0; o < 64; ++o) qout[o*HWQ + hw] = acc[o];

    // ---- fused depthwise conv ----
    int cl = tid >> 4, ox = tid & 15;
    #pragma unroll
    for (int q4 = 0; q4 < 4; ++q4) {
        __syncthreads();
        #pragma unroll
        for (int cc = 0; cc < 16; ++cc)
            sq[cc*256 + tid] = acc[q4*16 + cc];
        __syncthreads();
        int c = q4*16 + cl;
        float a = sdwb[c];
        const float* w = &swdw[c*16];
        const float* sp = sq + cl*256 + ox*4;
        #pragma unroll
        for (int ky = 0; ky < 4; ++ky)
            #pragma unroll
            for (int kx = 0; kx < 4; ++kx)
                a = fmaf(sp[ky*64 + kx], w[ky*4 + kx], a);
        sdw[ox*69 + c] = a;
    }
    __syncthreads();

    // ---- fused offset head ----
    {
        int warp = tid >> 5, lane = tid & 31;
        int half = lane >> 4, hl = lane & 15;
        int ln = warp*2 + half;
        float vv[4];
        float s1 = 0.f, s2 = 0.f;
        #pragma unroll
        for (int k = 0; k < 4; ++k) {
            vv[k] = sdw[ln*69 + hl*4 + k];
            s1 += vv[k]; s2 += vv[k]*vv[k];
        }
        #pragma unroll
        for (int off = 8; off; off >>= 1) {
            s1 += __shfl_xor_sync(0xffffffffu, s1, off);
            s2 += __shfl_xor_sync(0xffffffffu, s2, off);
        }
        float mu  = s1 * (1.f/64.f);
        float var = s2 * (1.f/64.f) - mu*mu;
        float rs  = rsqrtf(var + 1e-5f);
        float offy = 0.f, offx = 0.f;
        #pragma unroll
        for (int k = 0; k < 4; ++k) {
            int c = hl*4 + k;
            float t = (vv[k] - mu) * rs * __ldg(&lng[blk*64 + c]) + __ldg(&lnb[blk*64 + c]);
            float gl = 0.5f * t * (1.f + erff(t * 0.70710678118654752f));
            offy = fmaf(__ldg(&pww[blk*128 + c]),      gl, offy);
            offx = fmaf(__ldg(&pww[blk*128 + 64 + c]), gl, offx);
        }
        #pragma unroll
        for (int off = 8; off; off >>= 1) {
            offy += __shfl_xor_sync(0xffffffffu, offy, off);
            offx += __shfl_xor_sync(0xffffffffu, offx, off);
        }
        if (hl == 0) {
            int oy = tile;
            float refy = (2.f*((float)oy + 0.5f)) * (1.f/15.f) - 1.f;
            float refx = (2.f*((float)ln + 0.5f)) * (1.f/15.f) - 1.f;
            float py = fminf(fmaxf(offy + refy, -1.f), 1.f);
            float px = fminf(fmaxf(offx + refx, -1.f), 1.f);
            float ay = 31.5f*(1.f - py), ax = 31.5f*(1.f - px);
            float by0 = floorf(ay), bx0 = floorf(ax);
            int n = tile*16 + ln;
            g_BP[bb*NS + n]  = make_float4(by0*127.f + bx0, ay - by0, ax - bx0, 0.f);
            g_POS[bb*NS + n] = make_float2(py, px);
        }
    }
}

// ============================================================================
// Kernel B3: deformable gather + k/v projections.
// grid = 384 (3 blk * 8 b * 16 n-chunks of 16), 256 threads = (nl 16, cg 16).
// ============================================================================
__global__ __launch_bounds__(256) void k_gkv(
    const float* __restrict__ x0, const float* __restrict__ x1,
    const float* __restrict__ pkw, const float* __restrict__ pkb,
    const float* __restrict__ pvw, const float* __restrict__ pvb)
{
    extern __shared__ float sm[];
    float* buf  = sm;               // [16][65]
    float* skwT = sm + 16*65;       // [c][o] 4096
    float* svwT = skwT + 4096;      // 4096

    int bx = blockIdx.x;
    int chunk = bx & 15, b = (bx >> 4) & 7, blk = bx >> 7;
    const float* kvsrc = (blk == 2 ? x1 : x0) + (size_t)b * 128 * HWQ;
    int tid = threadIdx.x;
    int nl = tid & 15, cg = tid >> 4;
    int n = chunk*16 + nl;

    for (int i = tid; i < 4096; i += 256) {
        int o = i >> 6, c = i & 63;
        skwT[c*64 + o] = pkw[blk*4096 + i];
        svwT[c*64 + o] = pvw[blk*4096 + i];
    }

    float2 pos = g_POS[(blk*BD + b)*NS + n];
    float sy = (pos.x + 1.f)*31.5f, sx = (pos.y + 1.f)*31.5f;
    float fy = floorf(sy), fx = floorf(sx);
    int iy0 = (int)fy, ix0 = (int)fx;
    float wby = sy - fy, wbx = sx - fx;
    int iy1 = min(iy0 + 1, 63), ix1 = min(ix0 + 1, 63);
    float w00 = (1.f-wby)*(1.f-wbx), w01 = (1.f-wby)*wbx;
    float w10 = wby*(1.f-wbx),       w11 = wby*wbx;

    float tap[16];
    #pragma unroll
    for (int cc = 0; cc < 4; ++cc) {
        const float* ip = kvsrc + (size_t)(cg*4 + cc)*HWQ;
        tap[cc*4+0] = __ldg(&ip[iy0*64 + ix0]);
        tap[cc*4+1] = __ldg(&ip[iy0*64 + ix1]);
        tap[cc*4+2] = __ldg(&ip[iy1*64 + ix0]);
        tap[cc*4+3] = __ldg(&ip[iy1*64 + ix1]);
    }
    #pragma unroll
    for (int cc = 0; cc < 4; ++cc)
        buf[nl*65 + cg*4 + cc] = w00*tap[cc*4+0] + w01*tap[cc*4+1]
                               + w10*tap[cc*4+2] + w11*tap[cc*4+3];
    __syncthreads();

    float ak[4], av[4];
    #pragma unroll
    for (int oo = 0; oo < 4; ++oo) {
        ak[oo] = __ldg(&pkb[blk*64 + cg*4 + oo]);
        av[oo] = __ldg(&pvb[blk*64 + cg*4 + oo]);
    }
    #pragma unroll 8
    for (int c = 0; c < 64; ++c) {
        float xv = buf[nl*65 + c];
        float4 kw = *reinterpret_cast<const float4*>(&skwT[c*64 + cg*4]);
        float4 vw = *reinterpret_cast<const float4*>(&svwT[c*64 + cg*4]);
        ak[0] = fmaf(kw.x, xv, ak[0]); ak[1] = fmaf(kw.y, xv, ak[1]);
        ak[2] = fmaf(kw.z, xv, ak[2]); ak[3] = fmaf(kw.w, xv, ak[3]);
        av[0] = fmaf(vw.x, xv, av[0]); av[1] = fmaf(vw.y, xv, av[1]);
        av[2] = fmaf(vw.z, xv, av[2]); av[3] = fmaf(vw.w, xv, av[3]);
    }

    float* kout = g_K + (size_t)(blk*BD + b)*NCH*NS;
    float* vout = g_V + (size_t)(blk*BD + b)*NCH*NS;
    #pragma unroll
    for (int oo = 0; oo < 4; ++oo) {
        int o = cg*4 + oo;
        kout[o*NS + n] = ak[oo];
        vout[o*NS + n] = av[oo];
    }
}

// ============================================================================
// Kernel D: attention. Packed f32x2, depth-2 pipeline on the fp16 bias-table
// chain (1 L1 line per tap), tree-split QK chains, bare ex2.
// ============================================================================
__global__ __launch_bounds__(256, 2) void k_attn()
{
    extern __shared__ float sm[];
    float*      Ks    = sm;                            // 4096 floats
    float*      Vs    = sm + 4096;                     // 4096 floats
    ulonglong2* ppw   = (ulonglong2*)(sm + 8192);      // 256 * 16B
    int*        pbase = (int*)(sm + 8192 + 1024);      // 256

    int bx = blockIdx.x;
    int tile = bx & 7, head = (bx >> 3) & 3, bb = bx >> 5;
    int tid = threadIdx.x;

    const uint32_t* tab = (const uint32_t*)(g_TABH + (size_t)((bb >> 3)*4 + head) * TABP);

    const float* kg = g_K + (size_t)(bb*NCH + head*HCD) * NS;
    const float* vg = g_V + (size_t)(bb*NCH + head*HCD) * NS;
    #pragma unroll
    for (int c4 = 0; c4 < 4; ++c4) {
        float a0 = kg[(c4*4+0)*NS + tid], a1 = kg[(c4*4+1)*NS + tid];
        float a2 = kg[(c4*4+2)*NS + tid], a3 = kg[(c4*4+3)*NS + tid];
        reinterpret_cast<float4*>(Ks)[tid*4 + c4] = make_float4(a0,a1,a2,a3);
        a0 = vg[(c4*4+0)*NS + tid]; a1 = vg[(c4*4+1)*NS + tid];
        a2 = vg[(c4*4+2)*NS + tid]; a3 = vg[(c4*4+3)*NS + tid];
        reinterpret_cast<float4*>(Vs)[tid*4 + c4] = make_float4(a0,a1,a2,a3);
    }
    {
        float4 bp = g_BP[bb*NS + tid];
        float wy = bp.y, wx = bp.z;
        ulonglong2 w;
        // log2e folded into bias weights
        w.x = pk2(LOG2E*(1.f-wy)*(1.f-wx), LOG2E*(1.f-wy)*wx);
        w.y = pk2(LOG2E*wy*(1.f-wx),       LOG2E*wy*wx);
        ppw[tid] = w;
        pbase[tid] = (int)bp.x;
    }
    __syncthreads();

    int x = tid & 63, yp = tid >> 6;
    int y = tile*8 + yp*2;
    int m1 = y*64 + x;
    int rbase = y*127 + x;
    const float* qg = g_Q + (size_t)(bb*NCH + head*HCD) * HWQ;
    const float QS = 0.25f * LOG2E;
    u64t q1p[8], q2p[8];
    #pragma unroll
    for (int j = 0; j < 8; ++j) {
        q1p[j] = pk2(QS*qg[(2*j)*HWQ + m1],      QS*qg[(2*j+1)*HWQ + m1]);
        q2p[j] = pk2(QS*qg[(2*j)*HWQ + m1 + 64], QS*qg[(2*j+1)*HWQ + m1 + 64]);
    }

    u64t acc1p[8], acc2p[8];
    u64t zero = pk2(0.f, 0.f);
    #pragma unroll
    for (int j = 0; j < 8; ++j) { acc1p[j] = zero; acc2p[j] = zero; }
    float ss1 = 0.f, ss2 = 0.f;

    const ulonglong2* Ksu = (const ulonglong2*)Ks;
    const ulonglong2* Vsu = (const ulonglong2*)Vs;

    // ---- pipeline prologue: slots for n=0,1 (taps kept as raw half2 u32) ----
    ulonglong2 wpp[2];
    uint32_t th0[2], th1[2], th2[2];
    {
        int a0 = pbase[0] + rbase, a1 = pbase[1] + rbase;
        wpp[0] = ppw[0]; wpp[1] = ppw[1];
        th0[0] = __ldg(&tab[a0]); th1[0] = __ldg(&tab[a0+127]); th2[0] = __ldg(&tab[a0+254]);
        th0[1] = __ldg(&tab[a1]); th1[1] = __ldg(&tab[a1+127]); th2[1] = __ldg(&tab[a1+254]);
    }

    #pragma unroll 2
    for (int n = 0; n < 256; ++n) {
        int cur = n & 1;
        ulonglong2 wp = wpp[cur];
        u64t t0 = h2u64(th0[cur]);
        u64t t1 = h2u64(th1[cur]);
        u64t t2 = h2u64(th2[cur]);
        int np = n + 2;
        if (np < 256) {
            int a = pbase[np] + rbase;
            wpp[cur] = ppw[np];
            th0[cur] = __ldg(&tab[a]);
            th1[cur] = __ldg(&tab[a + 127]);
            th2[cur] = __ldg(&tab[a + 254]);
        }

        u64t b1p = fma2(wp.y, t1, mul2(wp.x, t0));
        u64t b2p = fma2(wp.y, t2, mul2(wp.x, t1));

        ulonglong2 kA = Ksu[n*4+0], kB = Ksu[n*4+1], kC = Ksu[n*4+2], kD = Ksu[n*4+3];
        u64t d1a = mul2(q1p[0], kA.x);
        d1a = fma2(q1p[1], kA.y, d1a); d1a = fma2(q1p[2], kB.x, d1a);
        d1a = fma2(q1p[3], kB.y, d1a);
        u64t d1b = mul2(q1p[4], kC.x);
        d1b = fma2(q1p[5], kC.y, d1b); d1b = fma2(q1p[6], kD.x, d1b);
        d1b = fma2(q1p[7], kD.y, d1b);
        u64t d2a = mul2(q2p[0], kA.x);
        d2a = fma2(q2p[1], kA.y, d2a); d2a = fma2(q2p[2], kB.x, d2a);
        d2a = fma2(q2p[3], kB.y, d2a);
        u64t d2b = mul2(q2p[4], kC.x);
        d2b = fma2(q2p[5], kC.y, d2b); d2b = fma2(q2p[6], kD.x, d2b);
        d2b = fma2(q2p[7], kD.y, d2b);

        float2 l1 = upk2(add2(add2(d1a, d1b), b1p));
        float2 l2 = upk2(add2(add2(d2a, d2b), b2p));
        float p1 = ex2f(l1.x + l1.y); ss1 += p1;
        float p2 = ex2f(l2.x + l2.y); ss2 += p2;
        u64t p1p = pk2(p1, p1), p2p = pk2(p2, p2);

        ulonglong2 vA = Vsu[n*4+0], vB = Vsu[n*4+1], vC = Vsu[n*4+2], vD = Vsu[n*4+3];
        acc1p[0] = fma2(p1p, vA.x, acc1p[0]); acc2p[0] = fma2(p2p, vA.x, acc2p[0]);
        acc1p[1] = fma2(p1p, vA.y, acc1p[1]); acc2p[1] = fma2(p2p, vA.y, acc2p[1]);
        acc1p[2] = fma2(p1p, vB.x, acc1p[2]); acc2p[2] = fma2(p2p, vB.x, acc2p[2]);
        acc1p[3] = fma2(p1p, vB.y, acc1p[3]); acc2p[3] = fma2(p2p, vB.y, acc2p[3]);
        acc1p[4] = fma2(p1p, vC.x, acc1p[4]); acc2p[4] = fma2(p2p, vC.x, acc2p[4]);
        acc1p[5] = fma2(p1p, vC.y, acc1p[5]); acc2p[5] = fma2(p2p, vC.y, acc2p[5]);
        acc1p[6] = fma2(p1p, vD.x, acc1p[6]); acc2p[6] = fma2(p2p, vD.x, acc2p[6]);
        acc1p[7] = fma2(p1p, vD.y, acc1p[7]); acc2p[7] = fma2(p2p, vD.y, acc2p[7]);
    }

    float i1 = 1.f / ss1, i2 = 1.f / ss2;
    float* og = g_O + (size_t)(bb*NCH + head*HCD) * HWQ;
    #pragma unroll
    for (int j = 0; j < 8; ++j) {
        float2 a1 = upk2(acc1p[j]), a2 = upk2(acc2p[j]);
        og[(2*j  )*HWQ + m1]      = a1.x * i1;
        og[(2*j+1)*HWQ + m1]      = a1.y * i1;
        og[(2*j  )*HWQ + m1 + 64] = a2.x * i2;
        og[(2*j+1)*HWQ + m1 + 64] = a2.y * i2;
    }
}

// ============================================================================
// Kernel E: output projection + residual, packed f32x2 with splatted weights.
// grid = 512 (lvl in {1,2} * 8 b * 32 tiles of 128 hw), 256 threads.
// ============================================================================
__global__ __launch_bounds__(256) void k_out(
    const float* __restrict__ x1, const float* __restrict__ x2,
    const float* __restrict__ poww, const float* __restrict__ pob,
    float* __restrict__ out)
{
    extern __shared__ u64t smw[];
    u64t* wp0 = smw;            // [c][o] packed, 4096
    u64t* wp1 = smw + 4096;     // 4096 (lvl2 only)
    u64t* bsp = smw + 8192;     // 64 packed biases

    int bx = blockIdx.x;
    int tile = bx & 31, b = (bx >> 5) & 7, lvl = 1 + (bx >> 8);
    const float* xl = (lvl == 1 ? x1 : x2) + (size_t)b * 128 * HWQ;
    float* outp = out + (size_t)(lvl*BD + b) * 128 * HWQ;
    int tid = threadIdx.x;
    int hp = tid & 63, oq = tid >> 6;
    int hw2 = tile*128 + hp*2;

    int blk0 = (lvl == 1) ? 0 : 1;
    int nb   = (lvl == 1) ? 1 : 2;

    for (int i = tid; i < 4096; i += 256) {
        int c = i >> 6, o = i & 63;
        float v0 = poww[blk0*4096 + o*64 + c];
        wp0[c*64 + o] = pk2(v0, v0);
        if (nb == 2) {
            float v1 = poww[(blk0+1)*4096 + o*64 + c];
            wp1[c*64 + o] = pk2(v1, v1);
        }
    }
    if (tid < 64) {
        float s = pob[blk0*64 + tid];
        if (nb == 2) s += pob[(blk0+1)*64 + tid];
        bsp[tid] = pk2(s, s);
    }
    __syncthreads();

    const float* o0 = g_O + (size_t)(blk0*BD + b) * NCH * HWQ;
    const float* o1 = g_O + (size_t)((blk0+1)*BD + b) * NCH * HWQ;

    u64t acc[16];
    #pragma unroll
    for (int j = 0; j < 16; ++j) {
        int o = oq*16 + j;
        u64t xlp = *reinterpret_cast<const u64t*>(xl + (size_t)(64 + o)*HWQ + hw2);
        acc[j] = add2(xlp, bsp[o]);
    }

    #pragma unroll 4
    for (int c = 0; c < 64; ++c) {
        u64t a0 = *reinterpret_cast<const u64t*>(o0 + (size_t)c*HWQ + hw2);
        const ulonglong2* wr = reinterpret_cast<const ulonglong2*>(&wp0[c*64 + oq*16]);
        #pragma unroll
        for (int j2 = 0; j2 < 8; ++j2) {
            ulonglong2 w = wr[j2];
            acc[j2*2+0] = fma2(w.x, a0, acc[j2*2+0]);
            acc[j2*2+1] = fma2(w.y, a0, acc[j2*2+1]);
        }
    }
    if (nb == 2) {
        #pragma unroll 4
        for (int c = 0; c < 64; ++c) {
            u64t a1 = *reinterpret_cast<const u64t*>(o1 + (size_t)c*HWQ + hw2);
            const ulonglong2* wr = reinterpret_cast<const ulonglong2*>(&wp1[c*64 + oq*16]);
            #pragma unroll
            for (int j2 = 0; j2 < 8; ++j2) {
                ulonglong2 w = wr[j2];
                acc[j2*2+0] = fma2(w.x, a1, acc[j2*2+0]);
                acc[j2*2+1] = fma2(w.y, a1, acc[j2*2+1]);
            }
        }
    }
    #pragma unroll
    for (int j = 0; j < 16; ++j) {
        int o = oq*16 + j;
        *reinterpret_cast<u64t*>(outp + (size_t)(64 + o)*HWQ + hw2) = acc[j];
    }
}

// ============================================================================
extern "C" void kernel_launch(void* const* d_in, const int* in_sizes, int n_in,
                              void* d_out, int out_size)
{
    const float* x0  = (const float*)d_in[0];
    const float* x1  = (const float*)d_in[1];
    const float* x2  = (const float*)d_in[2];
    const float* pqw = (const float*)d_in[3];
    const float* pqb = (const float*)d_in[4];
    const float* dww = (const float*)d_in[5];
    const float* dwb = (const float*)d_in[6];
    const float* lng = (const float*)d_in[7];
    const float* lnb = (const float*)d_in[8];
    const float* pww = (const float*)d_in[9];
    const float* pkw = (const float*)d_in[10];
    const float* pkb = (const float*)d_in[11];
    const float* pvw = (const float*)d_in[12];
    const float* pvb = (const float*)d_in[13];
    const float* pow_ = (const float*)d_in[14];
    const float* pob = (const float*)d_in[15];
    const float* rpe = (const float*)d_in[16];
    float* out = (float*)d_out;

    const int gkv_smem = (16*65 + 4096 + 4096) * 4;            // 36928 B
    const int d_smem   = 8192*4 + 256*16 + 256*4;              // 37888 B
    const int out_smem = (8192 + 64) * 8;                      // 66048 B
    cudaFuncSetAttribute(k_gkv,  cudaFuncAttributeMaxDynamicSharedMemorySize, gkv_smem);
    cudaFuncSetAttribute(k_attn, cudaFuncAttributeMaxDynamicSharedMemorySize, d_smem);
    cudaFuncSetAttribute(k_out,  cudaFuncAttributeMaxDynamicSharedMemorySize, out_smem);

    const size_t LVL = (size_t)BD * 128 * HWQ;
    const size_t BAT = (size_t)128 * HWQ;

    cudaMemcpyAsync(out, x0, LVL * 4, cudaMemcpyDeviceToDevice);
    for (int b = 0; b < BD; ++b)
        cudaMemcpyAsync(out + LVL + b*BAT, x1 + b*BAT, (BAT/2) * 4,
                        cudaMemcpyDeviceToDevice);
    for (int b = 0; b < BD; ++b)
        cudaMemcpyAsync(out + 2*LVL + b*BAT, x2 + b*BAT, (BAT/2) * 4,
                        cudaMemcpyDeviceToDevice);

    k_tab2<<<96, 256>>>(rpe);
    k_qproj_dw<<<384, 256>>>(x1, x2, pqw, pqb, dww, dwb, lng, lnb, pww);
    k_gkv<<<384, 256, gkv_smem>>>(x0, x1, pkw, pkb, pvw, pvb);
    k_attn<<<768, 256, d_smem>>>();
    k_out<<<512, 256, out_smem>>>(x1, x2, pow_, pob, out);
}

// round 13
// speedup vs baseline: 1.0885x; 1.0571x over previous
#include <cuda_runtime.h>
#include <cuda_fp16.h>
#include <math.h>
#include <stdint.h>

#define NBLK 3
#define BD 8
#define HWQ 4096   // 64*64
#define NCH 64     // NC (channels per DAT block)
#define NS  256    // Hk*Wk = 16*16
#define HCD 16     // head channels
#define TABN 16129 // 127*127
#define TABP 16384 // padded dual-table stride
#define LOG2E 1.4426950408889634f

// ---- static device scratch (no runtime allocation allowed) ----
__device__ float   g_Q[NBLK*BD*NCH*HWQ];   // q projections      [blk][b][c][hw]
__device__ float   g_O[NBLK*BD*NCH*HWQ];   // attention outputs  [blk][b][c][hw]
__device__ float   g_K[NBLK*BD*NCH*NS];    // keys   [blk][b][c][n]
__device__ float   g_V[NBLK*BD*NCH*NS];    // values [blk][b][c][n]
__device__ float4  g_BP[NBLK*BD*NS];       // bias params per n: (y0*127+x0, wy, wx, 0)
__device__ float2  g_POS[NBLK*BD*NS];      // normalized sample pos (py,px)
__device__ __half2 g_TABH[NBLK*4*TABP];    // dual RPE tables in fp16: (t[i], t[i+1])

// ---- packed f32x2 helpers (Blackwell sm_103a) ----
typedef unsigned long long u64t;
__device__ __forceinline__ u64t pk2(float a, float b) {
    u64t r; asm("mov.b64 %0, {%1, %2};" : "=l"(r) : "f"(a), "f"(b)); return r;
}
__device__ __forceinline__ float2 upk2(u64t v) {
    float x, y; asm("mov.b64 {%0, %1}, %2;" : "=f"(x), "=f"(y) : "l"(v));
    return make_float2(x, y);
}
__device__ __forceinline__ u64t fma2(u64t a, u64t b, u64t c) {
    u64t r; asm("fma.rn.f32x2 %0, %1, %2, %3;" : "=l"(r) : "l"(a), "l"(b), "l"(c));
    return r;
}
__device__ __forceinline__ u64t mul2(u64t a, u64t b) {
    u64t r; asm("mul.rn.f32x2 %0, %1, %2;" : "=l"(r) : "l"(a), "l"(b));
    return r;
}
__device__ __forceinline__ u64t add2(u64t a, u64t b) {
    u64t r; asm("add.rn.f32x2 %0, %1, %2;" : "=l"(r) : "l"(a), "l"(b));
    return r;
}
__device__ __forceinline__ float ex2f(float x) {
    float r; asm("ex2.approx.ftz.f32 %0, %1;" : "=f"(r) : "f"(x)); return r;
}
// half2 (as u32) -> packed f32x2 u64
__device__ __forceinline__ u64t h2u64(uint32_t h) {
    float2 f = __half22float2(*reinterpret_cast<__half2*>(&h));
    return pk2(f.x, f.y);
}

// ============================================================================
// Kernel C: single passthrough copy kernel (replaces 17 memcpy graph nodes).
// lvl0: full 128ch; lvl1/lvl2: ch 0..63. Total 2,097,152 float4.
// grid=2048 x 256 thr; 4 slices of exactly grid*block = 524288 each.
// ============================================================================
#define R0F4 1048576   // lvl0 floats4  (8*128*4096/4)
#define R1F4 524288    // lvl1 half     (8*64*4096/4)
#define BATF4 131072   // one image in float4 (128*4096/4)
#define HALF4 65536    // half image (64*4096/4)
#define LVLF4 1048576  // one level of out in float4
__global__ __launch_bounds__(256) void k_copy(
    const float4* __restrict__ x0, const float4* __restrict__ x1,
    const float4* __restrict__ x2, float4* __restrict__ out)
{
    int base = blockIdx.x*256 + threadIdx.x;    // 0 .. 524287
    #pragma unroll
    for (int k = 0; k < 4; ++k) {
        int idx = k*524288 + base;              // 0 .. 2097151 exactly
        if (idx < R0F4) {
            out[idx] = x0[idx];
        } else if (idx < R0F4 + R1F4) {
            int i = idx - R0F4;
            int b = i >> 16, r = i & (HALF4-1);
            out[LVLF4 + b*BATF4 + r] = x1[b*BATF4 + r];
        } else {
            int i = idx - (R0F4 + R1F4);
            int b = i >> 16, r = i & (HALF4-1);
            out[2*LVLF4 + b*BATF4 + r] = x2[b*BATF4 + r];
        }
    }
}

// ============================================================================
// Kernel T: build fp16 dual tables. grid = 12 tables * 8 chunks = 96
// ============================================================================
__global__ __launch_bounds__(256) void k_tab2(const float* __restrict__ rpe)
{
    int t = blockIdx.x >> 3, q = blockIdx.x & 7;
    const float* src = rpe + (size_t)t * TABN;
    __half2* dst = g_TABH + (size_t)t * TABP;
    #pragma unroll
    for (int k = 0; k < 8; ++k) {
        int i = q*2048 + k*256 + threadIdx.x;
        float a = (i < TABN)     ? src[i]   : 0.f;
        float b = (i+1 < TABN)   ? src[i+1] : 0.f;
        dst[i] = __floats2half2_rn(a, b);
    }
}

// ============================================================================
// Kernel A: q-projection + depthwise conv 4x4 s4 + LN/GELU/offset head fused.
// grid = 384 (3 blk * 8 b * 16 tiles of 4 image rows), 256 threads.
// ============================================================================
__global__ __launch_bounds__(256) void k_qproj_dw(
    const float* __restrict__ x1, const float* __restrict__ x2,
    const float* __restrict__ pqw, const float* __restrict__ pqb,
    const float* __restrict__ dww, const float* __restrict__ dwb,
    const float* __restrict__ lng, const float* __restrict__ lnb,
    const float* __restrict__ pww)
{
    __shared__ float wsT[64*64];
    __shared__ float bs[64];
    __shared__ float sq[16*256];
    __shared__ float swdw[64*16];
    __shared__ float sdwb[64];
    __shared__ float sdw[16*69];

    int bx = blockIdx.x;
    int tile = bx & 15, b = (bx >> 4) & 7, blk = bx >> 7;
    int bb = blk*BD + b;
    const float* xin = (blk == 0 ? x1 : x2) + (size_t)b * 128 * HWQ;
    int tid = threadIdx.x;

    for (int i = tid; i < 4096; i += 256) {
        int c = i >> 6, o = i & 63;
        wsT[c*64 + o] = pqw[blk*4096 + o*64 + c];
    }
    for (int i = tid; i < 1024; i += 256)
        swdw[i] = dww[blk*NCH*16 + i];
    if (tid < 64) {
        bs[tid]   = pqb[blk*64 + tid];
        sdwb[tid] = dwb[blk*64 + tid];
    }
    __syncthreads();

    int hw = tile*256 + tid;
    float* qout = g_Q + (size_t)bb * NCH * HWQ;

    float acc[64];
    #pragma unroll
    for (int o = 0; o < 64; ++o) acc[o] = bs[o];
    #pragma unroll 2
    for (int c = 0; c < 64; ++c) {
        float xv = __ldg(&xin[c*HWQ + hw]);
        const float4* wr = reinterpret_cast<const float4*>(&wsT[c*64]);
        #pragma unroll
        for (int o4 = 0; o4 < 16; ++o4) {
            float4 w = wr[o4];
            acc[o4*4+0] = fmaf(w.x, xv, acc[o4*4+0]);
            acc[o4*4+1] = fmaf(w.y, xv, acc[o4*4+1]);
            acc[o4*4+2] = fmaf(w.z, xv, acc[o4*4+2]);
            acc[o4*4+3] = fmaf(w.w, xv, acc[o4*4+3]);
        }
    }
    #pragma unroll
    for (int o = 0; o < 64; ++o) qout[o*HWQ + hw] = acc[o];

    // ---- fused depthwise conv ----
    int cl = tid >> 4, ox = tid & 15;
    #pragma unroll
    for (int q4 = 0; q4 < 4; ++q4) {
        __syncthreads();
        #pragma unroll
        for (int cc = 0; cc < 16; ++cc)
            sq[cc*256 + tid] = acc[q4*16 + cc];
        __syncthreads();
        int c = q4*16 + cl;
        float a = sdwb[c];
        const float* w = &swdw[c*16];
        const float* sp = sq + cl*256 + ox*4;
        #pragma unroll
        for (int ky = 0; ky < 4; ++ky)
            #pragma unroll
            for (int kx = 0; kx < 4; ++kx)
                a = fmaf(sp[ky*64 + kx], w[ky*4 + kx], a);
        sdw[ox*69 + c] = a;
    }
    __syncthreads();

    // ---- fused offset head ----
    {
        int warp = tid >> 5, lane = tid & 31;
        int half = lane >> 4, hl = lane & 15;
        int ln = warp*2 + half;
        float vv[4];
        float s1 = 0.f, s2 = 0.f;
        #pragma unroll
        for (int k = 0; k < 4; ++k) {
            vv[k] = sdw[ln*69 + hl*4 + k];
            s1 += vv[k]; s2 += vv[k]*vv[k];
        }
        #pragma unroll
        for (int off = 8; off; off >>= 1) {
            s1 += __shfl_xor_sync(0xffffffffu, s1, off);
            s2 += __shfl_xor_sync(0xffffffffu, s2, off);
        }
        float mu  = s1 * (1.f/64.f);
        float var = s2 * (1.f/64.f) - mu*mu;
        float rs  = rsqrtf(var + 1e-5f);
        float offy = 0.f, offx = 0.f;
        #pragma unroll
        for (int k = 0; k < 4; ++k) {
            int c = hl*4 + k;
            float t = (vv[k] - mu) * rs * __ldg(&lng[blk*64 + c]) + __ldg(&lnb[blk*64 + c]);
            float gl = 0.5f * t * (1.f + erff(t * 0.70710678118654752f));
            offy = fmaf(__ldg(&pww[blk*128 + c]),      gl, offy);
            offx = fmaf(__ldg(&pww[blk*128 + 64 + c]), gl, offx);
        }
        #pragma unroll
        for (int off = 8; off; off >>= 1) {
            offy += __shfl_xor_sync(0xffffffffu, offy, off);
            offx += __shfl_xor_sync(0xffffffffu, offx, off);
        }
        if (hl == 0) {
            int oy = tile;
            float refy = (2.f*((float)oy + 0.5f)) * (1.f/15.f) - 1.f;
            float refx = (2.f*((float)ln + 0.5f)) * (1.f/15.f) - 1.f;
            float py = fminf(fmaxf(offy + refy, -1.f), 1.f);
            float px = fminf(fmaxf(offx + refx, -1.f), 1.f);
            float ay = 31.5f*(1.f - py), ax = 31.5f*(1.f - px);
            float by0 = floorf(ay), bx0 = floorf(ax);
            int n = tile*16 + ln;
            g_BP[bb*NS + n]  = make_float4(by0*127.f + bx0, ay - by0, ax - bx0, 0.f);
            g_POS[bb*NS + n] = make_float2(py, px);
        }
    }
}

// ============================================================================
// Kernel B3: deformable gather + k/v projections.
// grid = 384 (3 blk * 8 b * 16 n-chunks of 16), 256 threads = (nl 16, cg 16).
// ============================================================================
__global__ __launch_bounds__(256) void k_gkv(
    const float* __restrict__ x0, const float* __restrict__ x1,
    const float* __restrict__ pkw, const float* __restrict__ pkb,
    const float* __restrict__ pvw, const float* __restrict__ pvb)
{
    extern __shared__ float sm[];
    float* buf  = sm;               // [16][65]
    float* skwT = sm + 16*65;       // [c][o] 4096
    float* svwT = skwT + 4096;      // 4096

    int bx = blockIdx.x;
    int chunk = bx & 15, b = (bx >> 4) & 7, blk = bx >> 7;
    const float* kvsrc = (blk == 2 ? x1 : x0) + (size_t)b * 128 * HWQ;
    int tid = threadIdx.x;
    int nl = tid & 15, cg = tid >> 4;
    int n = chunk*16 + nl;

    for (int i = tid; i < 4096; i += 256) {
        int o = i >> 6, c = i & 63;
        skwT[c*64 + o] = pkw[blk*4096 + i];
        svwT[c*64 + o] = pvw[blk*4096 + i];
    }

    float2 pos = g_POS[(blk*BD + b)*NS + n];
    float sy = (pos.x + 1.f)*31.5f, sx = (pos.y + 1.f)*31.5f;
    float fy = floorf(sy), fx = floorf(sx);
    int iy0 = (int)fy, ix0 = (int)fx;
    float wby = sy - fy, wbx = sx - fx;
    int iy1 = min(iy0 + 1, 63), ix1 = min(ix0 + 1, 63);
    float w00 = (1.f-wby)*(1.f-wbx), w01 = (1.f-wby)*wbx;
    float w10 = wby*(1.f-wbx),       w11 = wby*wbx;

    float tap[16];
    #pragma unroll
    for (int cc = 0; cc < 4; ++cc) {
        const float* ip = kvsrc + (size_t)(cg*4 + cc)*HWQ;
        tap[cc*4+0] = __ldg(&ip[iy0*64 + ix0]);
        tap[cc*4+1] = __ldg(&ip[iy0*64 + ix1]);
        tap[cc*4+2] = __ldg(&ip[iy1*64 + ix0]);
        tap[cc*4+3] = __ldg(&ip[iy1*64 + ix1]);
    }
    #pragma unroll
    for (int cc = 0; cc < 4; ++cc)
        buf[nl*65 + cg*4 + cc] = w00*tap[cc*4+0] + w01*tap[cc*4+1]
                               + w10*tap[cc*4+2] + w11*tap[cc*4+3];
    __syncthreads();

    float ak[4], av[4];
    #pragma unroll
    for (int oo = 0; oo < 4; ++oo) {
        ak[oo] = __ldg(&pkb[blk*64 + cg*4 + oo]);
        av[oo] = __ldg(&pvb[blk*64 + cg*4 + oo]);
    }
    #pragma unroll 8
    for (int c = 0; c < 64; ++c) {
        float xv = buf[nl*65 + c];
        float4 kw = *reinterpret_cast<const float4*>(&skwT[c*64 + cg*4]);
        float4 vw = *reinterpret_cast<const float4*>(&svwT[c*64 + cg*4]);
        ak[0] = fmaf(kw.x, xv, ak[0]); ak[1] = fmaf(kw.y, xv, ak[1]);
        ak[2] = fmaf(kw.z, xv, ak[2]); ak[3] = fmaf(kw.w, xv, ak[3]);
        av[0] = fmaf(vw.x, xv, av[0]); av[1] = fmaf(vw.y, xv, av[1]);
        av[2] = fmaf(vw.z, xv, av[2]); av[3] = fmaf(vw.w, xv, av[3]);
    }

    float* kout = g_K + (size_t)(blk*BD + b)*NCH*NS;
    float* vout = g_V + (size_t)(blk*BD + b)*NCH*NS;
    #pragma unroll
    for (int oo = 0; oo < 4; ++oo) {
        int o = cg*4 + oo;
        kout[o*NS + n] = ak[oo];
        vout[o*NS + n] = av[oo];
    }
}

// ============================================================================
// Kernel D: attention. Packed f32x2, depth-2 pipeline on fp16 bias tables,
// tree-split QK, bare ex2. Bias params = ONE float4 LDS (base bit-cast in .w,
// w11 reconstructed: weights scaled by log2e sum to log2e).
// ============================================================================
__global__ __launch_bounds__(256, 2) void k_attn()
{
    extern __shared__ float sm[];
    float*  Ks  = sm;                            // 4096 floats
    float*  Vs  = sm + 4096;                     // 4096 floats
    float4* ppw = (float4*)(sm + 8192);          // 256: (w00L,w01L,w10L,base-as-int)

    int bx = blockIdx.x;
    int tile = bx & 7, head = (bx >> 3) & 3, bb = bx >> 5;
    int tid = threadIdx.x;

    const uint32_t* tab = (const uint32_t*)(g_TABH + (size_t)((bb >> 3)*4 + head) * TABP);

    const float* kg = g_K + (size_t)(bb*NCH + head*HCD) * NS;
    const float* vg = g_V + (size_t)(bb*NCH + head*HCD) * NS;
    #pragma unroll
    for (int c4 = 0; c4 < 4; ++c4) {
        float a0 = kg[(c4*4+0)*NS + tid], a1 = kg[(c4*4+1)*NS + tid];
        float a2 = kg[(c4*4+2)*NS + tid], a3 = kg[(c4*4+3)*NS + tid];
        reinterpret_cast<float4*>(Ks)[tid*4 + c4] = make_float4(a0,a1,a2,a3);
        a0 = vg[(c4*4+0)*NS + tid]; a1 = vg[(c4*4+1)*NS + tid];
        a2 = vg[(c4*4+2)*NS + tid]; a3 = vg[(c4*4+3)*NS + tid];
        reinterpret_cast<float4*>(Vs)[tid*4 + c4] = make_float4(a0,a1,a2,a3);
    }
    {
        float4 bp = g_BP[bb*NS + tid];
        float wy = bp.y, wx = bp.z;
        ppw[tid] = make_float4(LOG2E*(1.f-wy)*(1.f-wx),
                               LOG2E*(1.f-wy)*wx,
                               LOG2E*wy*(1.f-wx),
                               __int_as_float((int)bp.x));
    }
    __syncthreads();

    int x = tid & 63, yp = tid >> 6;
    int y = tile*8 + yp*2;
    int m1 = y*64 + x;
    int rbase = y*127 + x;
    const float* qg = g_Q + (size_t)(bb*NCH + head*HCD) * HWQ;
    const float QS = 0.25f * LOG2E;
    u64t q1p[8], q2p[8];
    #pragma unroll
    for (int j = 0; j < 8; ++j) {
        q1p[j] = pk2(QS*qg[(2*j)*HWQ + m1],      QS*qg[(2*j+1)*HWQ + m1]);
        q2p[j] = pk2(QS*qg[(2*j)*HWQ + m1 + 64], QS*qg[(2*j+1)*HWQ + m1 + 64]);
    }

    u64t acc1p[8], acc2p[8];
    u64t zero = pk2(0.f, 0.f);
    #pragma unroll
    for (int j = 0; j < 8; ++j) { acc1p[j] = zero; acc2p[j] = zero; }
    float ss1 = 0.f, ss2 = 0.f;

    const ulonglong2* Ksu = (const ulonglong2*)Ks;
    const ulonglong2* Vsu = (const ulonglong2*)Vs;

    // ---- pipeline prologue: slots for n=0,1 ----
    float4 wpp[2];
    uint32_t th0[2], th1[2], th2[2];
    {
        wpp[0] = ppw[0]; wpp[1] = ppw[1];
        int a0 = __float_as_int(wpp[0].w) + rbase;
        int a1 = __float_as_int(wpp[1].w) + rbase;
        th0[0] = __ldg(&tab[a0]); th1[0] = __ldg(&tab[a0+127]); th2[0] = __ldg(&tab[a0+254]);
        th0[1] = __ldg(&tab[a1]); th1[1] = __ldg(&tab[a1+127]); th2[1] = __ldg(&tab[a1+254]);
    }

    #pragma unroll 2
    for (int n = 0; n < 256; ++n) {
        int cur = n & 1;
        float4 wp = wpp[cur];
        u64t t0 = h2u64(th0[cur]);
        u64t t1 = h2u64(th1[cur]);
        u64t t2 = h2u64(th2[cur]);
        int np = n + 2;
        if (np < 256) {
            float4 w2 = ppw[np];
            int a = __float_as_int(w2.w) + rbase;
            wpp[cur] = w2;
            th0[cur] = __ldg(&tab[a]);
            th1[cur] = __ldg(&tab[a + 127]);
            th2[cur] = __ldg(&tab[a + 254]);
        }

        float w11 = LOG2E - wp.x - wp.y - wp.z;
        u64t wA = pk2(wp.x, wp.y);
        u64t wB = pk2(wp.z, w11);
        u64t b1p = fma2(wB, t1, mul2(wA, t0));
        u64t b2p = fma2(wB, t2, mul2(wA, t1));

        ulonglong2 kA = Ksu[n*4+0], kB = Ksu[n*4+1], kC = Ksu[n*4+2], kD = Ksu[n*4+3];
        u64t d1a = mul2(q1p[0], kA.x);
        d1a = fma2(q1p[1], kA.y, d1a); d1a = fma2(q1p[2], kB.x, d1a);
        d1a = fma2(q1p[3], kB.y, d1a);
        u64t d1b = mul2(q1p[4], kC.x);
        d1b = fma2(q1p[5], kC.y, d1b); d1b = fma2(q1p[6], kD.x, d1b);
        d1b = fma2(q1p[7], kD.y, d1b);
        u64t d2a = mul2(q2p[0], kA.x);
        d2a = fma2(q2p[1], kA.y, d2a); d2a = fma2(q2p[2], kB.x, d2a);
        d2a = fma2(q2p[3], kB.y, d2a);
        u64t d2b = mul2(q2p[4], kC.x);
        d2b = fma2(q2p[5], kC.y, d2b); d2b = fma2(q2p[6], kD.x, d2b);
        d2b = fma2(q2p[7], kD.y, d2b);

        float2 l1 = upk2(add2(add2(d1a, d1b), b1p));
        float2 l2 = upk2(add2(add2(d2a, d2b), b2p));
        float p1 = ex2f(l1.x + l1.y); ss1 += p1;
        float p2 = ex2f(l2.x + l2.y); ss2 += p2;
        u64t p1p = pk2(p1, p1), p2p = pk2(p2, p2);

        ulonglong2 vA = Vsu[n*4+0], vB = Vsu[n*4+1], vC = Vsu[n*4+2], vD = Vsu[n*4+3];
        acc1p[0] = fma2(p1p, vA.x, acc1p[0]); acc2p[0] = fma2(p2p, vA.x, acc2p[0]);
        acc1p[1] = fma2(p1p, vA.y, acc1p[1]); acc2p[1] = fma2(p2p, vA.y, acc2p[1]);
        acc1p[2] = fma2(p1p, vB.x, acc1p[2]); acc2p[2] = fma2(p2p, vB.x, acc2p[2]);
        acc1p[3] = fma2(p1p, vB.y, acc1p[3]); acc2p[3] = fma2(p2p, vB.y, acc2p[3]);
        acc1p[4] = fma2(p1p, vC.x, acc1p[4]); acc2p[4] = fma2(p2p, vC.x, acc2p[4]);
        acc1p[5] = fma2(p1p, vC.y, acc1p[5]); acc2p[5] = fma2(p2p, vC.y, acc2p[5]);
        acc1p[6] = fma2(p1p, vD.x, acc1p[6]); acc2p[6] = fma2(p2p, vD.x, acc2p[6]);
        acc1p[7] = fma2(p1p, vD.y, acc1p[7]); acc2p[7] = fma2(p2p, vD.y, acc2p[7]);
    }

    float i1 = 1.f / ss1, i2 = 1.f / ss2;
    float* og = g_O + (size_t)(bb*NCH + head*HCD) * HWQ;
    #pragma unroll
    for (int j = 0; j < 8; ++j) {
        float2 a1 = upk2(acc1p[j]), a2 = upk2(acc2p[j]);
        og[(2*j  )*HWQ + m1]      = a1.x * i1;
        og[(2*j+1)*HWQ + m1]      = a1.y * i1;
        og[(2*j  )*HWQ + m1 + 64] = a2.x * i2;
        og[(2*j+1)*HWQ + m1 + 64] = a2.y * i2;
    }
}

// ============================================================================
// Kernel E: output projection + residual, packed f32x2 with splatted weights.
// grid = 512 (lvl in {1,2} * 8 b * 32 tiles of 128 hw), 256 threads.
// ============================================================================
__global__ __launch_bounds__(256) void k_out(
    const float* __restrict__ x1, const float* __restrict__ x2,
    const float* __restrict__ poww, const float* __restrict__ pob,
    float* __restrict__ out)
{
    extern __shared__ u64t smw[];
    u64t* wp0 = smw;            // [c][o] packed, 4096
    u64t* wp1 = smw + 4096;     // 4096 (lvl2 only)
    u64t* bsp = smw + 8192;     // 64 packed biases

    int bx = blockIdx.x;
    int tile = bx & 31, b = (bx >> 5) & 7, lvl = 1 + (bx >> 8);
    const float* xl = (lvl == 1 ? x1 : x2) + (size_t)b * 128 * HWQ;
    float* outp = out + (size_t)(lvl*BD + b) * 128 * HWQ;
    int tid = threadIdx.x;
    int hp = tid & 63, oq = tid >> 6;
    int hw2 = tile*128 + hp*2;

    int blk0 = (lvl == 1) ? 0 : 1;
    int nb   = (lvl == 1) ? 1 : 2;

    for (int i = tid; i < 4096; i += 256) {
        int c = i >> 6, o = i & 63;
        float v0 = poww[blk0*4096 + o*64 + c];
        wp0[c*64 + o] = pk2(v0, v0);
        if (nb == 2) {
            float v1 = poww[(blk0+1)*4096 + o*64 + c];
            wp1[c*64 + o] = pk2(v1, v1);
        }
    }
    if (tid < 64) {
        float s = pob[blk0*64 + tid];
        if (nb == 2) s += pob[(blk0+1)*64 + tid];
        bsp[tid] = pk2(s, s);
    }
    __syncthreads();

    const float* o0 = g_O + (size_t)(blk0*BD + b) * NCH * HWQ;
    const float* o1 = g_O + (size_t)((blk0+1)*BD + b) * NCH * HWQ;

    u64t acc[16];
    #pragma unroll
    for (int j = 0; j < 16; ++j) {
        int o = oq*16 + j;
        u64t xlp = *reinterpret_cast<const u64t*>(xl + (size_t)(64 + o)*HWQ + hw2);
        acc[j] = add2(xlp, bsp[o]);
    }

    #pragma unroll 4
    for (int c = 0; c < 64; ++c) {
        u64t a0 = *reinterpret_cast<const u64t*>(o0 + (size_t)c*HWQ + hw2);
        const ulonglong2* wr = reinterpret_cast<const ulonglong2*>(&wp0[c*64 + oq*16]);
        #pragma unroll
        for (int j2 = 0; j2 < 8; ++j2) {
            ulonglong2 w = wr[j2];
            acc[j2*2+0] = fma2(w.x, a0, acc[j2*2+0]);
            acc[j2*2+1] = fma2(w.y, a0, acc[j2*2+1]);
        }
    }
    if (nb == 2) {
        #pragma unroll 4
        for (int c = 0; c < 64; ++c) {
            u64t a1 = *reinterpret_cast<const u64t*>(o1 + (size_t)c*HWQ + hw2);
            const ulonglong2* wr = reinterpret_cast<const ulonglong2*>(&wp1[c*64 + oq*16]);
            #pragma unroll
            for (int j2 = 0; j2 < 8; ++j2) {
                ulonglong2 w = wr[j2];
                acc[j2*2+0] = fma2(w.x, a1, acc[j2*2+0]);
                acc[j2*2+1] = fma2(w.y, a1, acc[j2*2+1]);
            }
        }
    }
    #pragma unroll
    for (int j = 0; j < 16; ++j) {
        int o = oq*16 + j;
        *reinterpret_cast<u64t*>(outp + (size_t)(64 + o)*HWQ + hw2) = acc[j];
    }
}

// ============================================================================
extern "C" void kernel_launch(void* const* d_in, const int* in_sizes, int n_in,
                              void* d_out, int out_size)
{
    const float* x0  = (const float*)d_in[0];
    const float* x1  = (const float*)d_in[1];
    const float* x2  = (const float*)d_in[2];
    const float* pqw = (const float*)d_in[3];
    const float* pqb = (const float*)d_in[4];
    const float* dww = (const float*)d_in[5];
    const float* dwb = (const float*)d_in[6];
    const float* lng = (const float*)d_in[7];
    const float* lnb = (const float*)d_in[8];
    const float* pww = (const float*)d_in[9];
    const float* pkw = (const float*)d_in[10];
    const float* pkb = (const float*)d_in[11];
    const float* pvw = (const float*)d_in[12];
    const float* pvb = (const float*)d_in[13];
    const float* pow_ = (const float*)d_in[14];
    const float* pob = (const float*)d_in[15];
    const float* rpe = (const float*)d_in[16];
    float* out = (float*)d_out;

    const int gkv_smem = (16*65 + 4096 + 4096) * 4;            // 36928 B
    const int d_smem   = 8192*4 + 256*16;                      // 36864 B
    const int out_smem = (8192 + 64) * 8;                      // 66048 B
    cudaFuncSetAttribute(k_gkv,  cudaFuncAttributeMaxDynamicSharedMemorySize, gkv_smem);
    cudaFuncSetAttribute(k_attn, cudaFuncAttributeMaxDynamicSharedMemorySize, d_smem);
    cudaFuncSetAttribute(k_out,  cudaFuncAttributeMaxDynamicSharedMemorySize, out_smem);

    k_copy<<<2048, 256>>>((const float4*)x0, (const float4*)x1,
                          (const float4*)x2, (float4*)out);
    k_tab2<<<96, 256>>>(rpe);
    k_qproj_dw<<<384, 256>>>(x1, x2, pqw, pqb, dww, dwb, lng, lnb, pww);
    k_gkv<<<384, 256, gkv_smem>>>(x0, x1, pkw, pkb, pvw, pvb);
    k_attn<<<768, 256, d_smem>>>();
    k_out<<<512, 256, out_smem>>>(x1, x2, pow_, pob, out);
}